// round 12
// baseline (speedup 1.0000x reference)
#include <cuda_runtime.h>
#include <cstdint>

#define FULL 0xffffffffu
#define N_OPS_C 20
#define N_QUBITS_C 8

using u64 = unsigned long long;

// ===========================================================================
// Compile-time reproduction of np.random.RandomState(0) draws for _RL_OPS
// (validated across R1/R3/R4/R5/R6/R7/R11: rel_err ~2e-7..3.5e-7).
// ===========================================================================
struct OpsArr { int op[N_OPS_C]; };  // kind | (w0<<2) | (w1<<5); 0=rx 1=ry 2=rz 3=cnot

struct CxRng {
    uint32_t mt[624]; int mti;
    constexpr CxRng() : mt{}, mti(624) {
        mt[0] = 0u;
        for (int i = 1; i < 624; i++)
            mt[i] = 1812433253u * (mt[i - 1] ^ (mt[i - 1] >> 30)) + (uint32_t)i;
    }
    constexpr uint32_t next() {
        if (mti >= 624) {
            for (int i = 0; i < 624; i++) {
                uint32_t y = (mt[i] & 0x80000000u) | (mt[(i + 1) % 624] & 0x7fffffffu);
                mt[i] = mt[(i + 397) % 624] ^ (y >> 1) ^ ((y & 1u) ? 0x9908b0dfu : 0u);
            }
            mti = 0;
        }
        uint32_t y = mt[mti++];
        y ^= y >> 11;
        y ^= (y << 7) & 0x9d2c5680u;
        y ^= (y << 15) & 0xefc60000u;
        y ^= y >> 18;
        return y;
    }
    constexpr uint32_t interval(uint32_t mx) {
        if (mx == 0u) return 0u;
        uint32_t mask = mx;
        mask |= mask >> 1; mask |= mask >> 2; mask |= mask >> 4;
        mask |= mask >> 8; mask |= mask >> 16;
        uint32_t v = next() & mask;
        while (v > mx) v = next() & mask;
        return v;
    }
};

constexpr OpsArr build_ops_cx() {
    CxRng rng{};
    OpsArr ol{};
    for (int k = 0; k < N_OPS_C; k++) {
        int kd = (int)(rng.next() & 3u);
        int w0 = 0, w1 = 0;
        if (kd == 3) {
            int perm[8] = {0, 1, 2, 3, 4, 5, 6, 7};
            for (int i = 7; i > 0; i--) {
                uint32_t j = rng.interval((uint32_t)i);
                int t = perm[i]; perm[i] = perm[(int)j]; perm[(int)j] = t;
            }
            w0 = perm[0]; w1 = perm[1];
        } else {
            w0 = (int)(rng.next() & 7u);
        }
        ol.op[k] = kd | (w0 << 2) | (w1 << 5);
    }
    return ol;
}

constexpr OpsArr OPS = build_ops_cx();

// ===========================================================================
// Compile-time circuit compiler v3 = v2 (CU fusion + commutation deferral)
// + wire->bit permutation chosen to minimize shuffle passes.
// Emission ops:
//   0 = plain CNOT           (ew=ctl, ew2=tgt)
//   1 = fused SU(2) U        (ew=wire, ew2=matrix idx)
//   2 = singleton rotation   (ew=wire, ew2=k, ekind=kind)
//   3 = CU = CNOT o U(tgt)   (ew=ctl, ew2=tgt, ekind=matrix idx)
// ===========================================================================
struct Plan {
    int n_emit;
    int etype[48], ew[48], ew2[48], ekind[48];
    int n_mat;
    int mlen[32], mk[32][24], mkind[32][24];
    int pre_len[8], pre_k[8][20], pre_kind[8][20];
};

constexpr Plan build_plan() {
    Plan P{};
    int plen[8] = {}; int pk[8][20] = {}; int pkd[8][20] = {};
    bool seen[8] = {};
    for (int k = 0; k < N_OPS_C; k++) {
        int o = OPS.op[k]; int kd = o & 3;
        int w0 = (o >> 2) & 7, w1 = (o >> 5) & 7;
        if (kd != 3) {
            pk[w0][plen[w0]] = k; pkd[w0][plen[w0]] = kd; plen[w0]++;
            continue;
        }
        int c = w0, t = w1;
        // --- ctl side: absorb (first touch) or flush non-RZ prefix ---
        if (!seen[c]) {
            P.pre_len[c] = plen[c];
            for (int i = 0; i < plen[c]; i++) {
                P.pre_k[c][i] = pk[c][i]; P.pre_kind[c][i] = pkd[c][i];
            }
            plen[c] = 0;
        } else {
            int split = plen[c];
            while (split > 0 && pkd[c][split - 1] == 2) split--;  // defer RZ suffix
            if (split == 1) {
                P.etype[P.n_emit] = 2; P.ew[P.n_emit] = c;
                P.ew2[P.n_emit] = pk[c][0]; P.ekind[P.n_emit] = pkd[c][0];
                P.n_emit++;
            } else if (split > 1) {
                int m = P.n_mat++;
                P.mlen[m] = split;
                for (int i = 0; i < split; i++) {
                    P.mk[m][i] = pk[c][i]; P.mkind[m][i] = pkd[c][i];
                }
                P.etype[P.n_emit] = 1; P.ew[P.n_emit] = c; P.ew2[P.n_emit] = m;
                P.n_emit++;
            }
            for (int i = split; i < plen[c]; i++) {
                pk[c][i - split] = pk[c][i]; pkd[c][i - split] = pkd[c][i];
            }
            plen[c] -= split;
        }
        seen[c] = true;
        // --- tgt side: absorb (first touch) or CU-fuse non-RX prefix ---
        bool cu = false;
        if (!seen[t]) {
            P.pre_len[t] = plen[t];
            for (int i = 0; i < plen[t]; i++) {
                P.pre_k[t][i] = pk[t][i]; P.pre_kind[t][i] = pkd[t][i];
            }
            plen[t] = 0;
        } else {
            int split = plen[t];
            while (split > 0 && pkd[t][split - 1] == 0) split--;  // defer RX suffix
            if (split > 0) {
                int m = P.n_mat++;
                P.mlen[m] = split;
                for (int i = 0; i < split; i++) {
                    P.mk[m][i] = pk[t][i]; P.mkind[m][i] = pkd[t][i];
                }
                P.etype[P.n_emit] = 3; P.ew[P.n_emit] = c; P.ew2[P.n_emit] = t;
                P.ekind[P.n_emit] = m; P.n_emit++;
                cu = true;
            }
            for (int i = split; i < plen[t]; i++) {
                pk[t][i - split] = pk[t][i]; pkd[t][i - split] = pkd[t][i];
            }
            plen[t] -= split;
        }
        seen[t] = true;
        if (!cu) {
            P.etype[P.n_emit] = 0; P.ew[P.n_emit] = c; P.ew2[P.n_emit] = t;
            P.n_emit++;
        }
    }
    // Final per-wire U = trailing pendings + RX(theta_rx) + RY(theta_ry)
    for (int w = 0; w < 8; w++) {
        int m = P.n_mat++;
        int L = 0;
        for (int i = 0; i < plen[w]; i++) {
            P.mk[m][L] = pk[w][i]; P.mkind[m][L] = pkd[w][i]; L++;
        }
        P.mk[m][L] = -1; P.mkind[m][L] = 0; L++;
        P.mk[m][L] = -2; P.mkind[m][L] = 1; L++;
        P.mlen[m] = L;
        P.etype[P.n_emit] = 1; P.ew[P.n_emit] = w; P.ew2[P.n_emit] = m;
        P.n_emit++;
    }
    return P;
}

constexpr Plan PLAN = build_plan();
__constant__ Plan d_PLAN = build_plan();
constexpr int NMAT  = PLAN.n_mat;
constexpr int NEMIT = PLAN.n_emit;

// ---- Wire->bit permutation: minimize lane (shuffle-bearing) passes ----
struct Perm { int wbit[8]; int wofb[8]; };

constexpr Perm build_perm() {
    int wgt[8] = {};
    for (int e = 0; e < PLAN.n_emit; e++) {
        int ty = PLAN.etype[e];
        if (ty == 0)      wgt[PLAN.ew2[e]]++;                        // CNOT tgt
        else if (ty == 1) wgt[PLAN.ew[e]]++;                         // U
        else if (ty == 2) { if (PLAN.ekind[e] != 2) wgt[PLAN.ew[e]]++; }  // non-RZ rot
        else              wgt[PLAN.ew2[e]]++;                        // CU tgt
    }
    Perm P{};
    int order[8] = {0, 1, 2, 3, 4, 5, 6, 7};
    for (int i = 0; i < 8; i++) {                 // selection sort, weight desc
        int best = i;
        for (int k = i + 1; k < 8; k++)
            if (wgt[order[k]] > wgt[order[best]]) best = k;
        int t = order[i]; order[i] = order[best]; order[best] = t;
    }
    for (int i = 0; i < 8; i++) { P.wbit[order[i]] = i; P.wofb[i] = order[i]; }
    return P;
}

constexpr Perm PERM = build_perm();
// Packed scalar copies for DEVICE-CODE runtime use (constexpr struct members
// can't be odr-used in device code; scalar constexpr ints fold to immediates).
constexpr int WOFB_HI = PERM.wofb[4] | (PERM.wofb[5] << 8)
                      | (PERM.wofb[6] << 16) | (PERM.wofb[7] << 24);
constexpr int WOFB_LO0 = PERM.wofb[0];
constexpr int WOFB_LO1 = PERM.wofb[1];
constexpr int WOFB_LO2 = PERM.wofb[2];
constexpr int WOFB_LO3 = PERM.wofb[3];

constexpr int first_lane_cplx() {
    for (int w = 0; w < 8; w++)
        if (PLAN.pre_len[w] > 0 && PERM.wbit[w] >= 4) return w;
    return -1;
}
constexpr int first_local_cplx() {
    for (int w = 0; w < 8; w++)
        if (PLAN.pre_len[w] > 0 && PERM.wbit[w] < 4) return w;
    return -1;
}
constexpr int FT = first_lane_cplx();
constexpr int FJ = first_local_cplx();

// ===========================================================================
// Packed f32x2 primitives. Amplitude = u64 packed (re = lo, im = hi).
// ===========================================================================
__device__ __forceinline__ u64 pk2(float lo, float hi) {
    u64 r; asm("mov.b64 %0, {%1, %2};" : "=l"(r) : "f"(lo), "f"(hi)); return r;
}
__device__ __forceinline__ void upk2(u64 v, float& lo, float& hi) {
    asm("mov.b64 {%0, %1}, %2;" : "=f"(lo), "=f"(hi) : "l"(v));
}
__device__ __forceinline__ u64 sw2(u64 v) {
    u64 r;
    asm("{\n\t.reg .b32 a, b;\n\tmov.b64 {a, b}, %1;\n\tmov.b64 %0, {b, a};\n\t}"
        : "=l"(r) : "l"(v));
    return r;
}
__device__ __forceinline__ u64 fma2(u64 a, u64 b, u64 c) {
    u64 d; asm("fma.rn.f32x2 %0, %1, %2, %3;" : "=l"(d) : "l"(a), "l"(b), "l"(c)); return d;
}
__device__ __forceinline__ u64 mul2(u64 a, u64 b) {
    u64 d; asm("mul.rn.f32x2 %0, %1, %2;" : "=l"(d) : "l"(a), "l"(b)); return d;
}
__device__ __forceinline__ u64 cmul(u64 p, u64 q) {
    float pr, pi_; upk2(p, pr, pi_);
    return fma2(pk2(-pi_, pi_), sw2(q), mul2(pk2(pr, pr), q));
}
__device__ __forceinline__ u64 shfl_pk(u64 v, int m) {
    float lo, hi; upk2(v, lo, hi);
    float plo = __shfl_xor_sync(FULL, lo, m);
    float phi = __shfl_xor_sync(FULL, hi, m);
    return pk2(plo, phi);
}
__device__ __forceinline__ u64 shfl_pk_sw(u64 v, int m) {
    float lo, hi; upk2(v, lo, hi);
    float plo = __shfl_xor_sync(FULL, lo, m);
    float phi = __shfl_xor_sync(FULL, hi, m);
    return pk2(phi, plo);
}
__device__ __forceinline__ void shfl_pk_both(u64 v, int m, u64& q, u64& qsw) {
    float lo, hi; upk2(v, lo, hi);
    float plo = __shfl_xor_sync(FULL, lo, m);
    float phi = __shfl_xor_sync(FULL, hi, m);
    q = pk2(plo, phi); qsw = pk2(phi, plo);
}

// ===========================================================================
// Layout: 2 items per warp, 16 lanes per item (group bit = lane bit 4).
// Amplitude index bits: [7:4] = sublane t (lane bits 3..0), [3:0] = local j.
// Wire w <-> bit PERM.wbit[w]. BIT>=4: lane gate; BIT<4: register-local.
// ===========================================================================

template<int BIT>
__device__ __forceinline__ void rx_g(u64 (&v)[16], u64 CC, u64 SPN, int lane) {
    if constexpr (BIT >= 4) {
        constexpr int m = 1 << (BIT - 4);
#pragma unroll
        for (int j = 0; j < 16; j++) {
            u64 psw = shfl_pk_sw(v[j], m);
            v[j] = fma2(SPN, psw, mul2(CC, v[j]));
        }
    } else {
        constexpr int m = 1 << BIT;
#pragma unroll
        for (int j0 = 0; j0 < 16; j0++) {
            if ((j0 & m) == 0) {
                const int j1 = j0 | m;
                u64 sw0 = sw2(v[j0]), sw1 = sw2(v[j1]);
                v[j0] = fma2(SPN, sw1, mul2(CC, v[j0]));
                v[j1] = fma2(SPN, sw0, mul2(CC, v[j1]));
            }
        }
    }
}

template<int BIT>
__device__ __forceinline__ void ry_g(u64 (&v)[16], u64 CC, u64 SS, u64 SN, int lane) {
    if constexpr (BIT >= 4) {
        constexpr int m = 1 << (BIT - 4);
        u64 ssP = ((lane >> (BIT - 4)) & 1) ? SS : SN;
#pragma unroll
        for (int j = 0; j < 16; j++) {
            u64 p = shfl_pk(v[j], m);
            v[j] = fma2(ssP, p, mul2(CC, v[j]));
        }
    } else {
        constexpr int m = 1 << BIT;
#pragma unroll
        for (int j0 = 0; j0 < 16; j0++) {
            if ((j0 & m) == 0) {
                const int j1 = j0 | m;
                u64 v0 = v[j0], v1 = v[j1];
                v[j0] = fma2(SN, v1, mul2(CC, v0));
                v[j1] = fma2(SS, v0, mul2(CC, v1));
            }
        }
    }
}

template<int BIT>
__device__ __forceinline__ void rz_g(u64 (&v)[16], u64 CC, u64 SPN, u64 NSP, int lane) {
    if constexpr (BIT >= 4) {
        u64 zc = ((lane >> (BIT - 4)) & 1) ? NSP : SPN;
#pragma unroll
        for (int j = 0; j < 16; j++)
            v[j] = fma2(zc, sw2(v[j]), mul2(CC, v[j]));
    } else {
        constexpr int m = 1 << BIT;
#pragma unroll
        for (int j = 0; j < 16; j++) {
            u64 zc = (j & m) ? NSP : SPN;
            v[j] = fma2(zc, sw2(v[j]), mul2(CC, v[j]));
        }
    }
}

template<int CB, int TB>
__device__ __forceinline__ void cnot_g(u64 (&v)[16], int lane) {
    if constexpr (CB >= 4 && TB >= 4) {
        constexpr int mt = 1 << (TB - 4);
        bool ctl = (lane >> (CB - 4)) & 1;
#pragma unroll
        for (int j = 0; j < 16; j++) {
            u64 q = shfl_pk(v[j], mt);
            if (ctl) v[j] = q;
        }
    } else if constexpr (CB >= 4 && TB < 4) {
        constexpr int mt = 1 << TB;
        bool ctl = (lane >> (CB - 4)) & 1;
#pragma unroll
        for (int j0 = 0; j0 < 16; j0++) {
            if ((j0 & mt) == 0) {
                const int j1 = j0 | mt;
                u64 a = v[j0], b = v[j1];
                v[j0] = ctl ? b : a;
                v[j1] = ctl ? a : b;
            }
        }
    } else if constexpr (CB < 4 && TB >= 4) {
        constexpr int mc = 1 << CB;
        constexpr int mt = 1 << (TB - 4);
#pragma unroll
        for (int j = 0; j < 16; j++) {
            if (j & mc)
                v[j] = shfl_pk(v[j], mt);
        }
    } else {
        constexpr int mc = 1 << CB;
        constexpr int mt = 1 << TB;
#pragma unroll
        for (int j0 = 0; j0 < 16; j0++) {
            if ((j0 & mc) && !(j0 & mt)) {
                const int j1 = j0 | mt;
                u64 t = v[j0]; v[j0] = v[j1]; v[j1] = t;
            }
        }
    }
}

// General SU(2) gate U = [[ar+i*ai, br+i*bi], [-br+i*bi, ar-i*ai]]
template<int BIT>
__device__ __forceinline__ void u_g(u64 (&v)[16],
                                    u64 AR2, u64 AIP, u64 AIN,
                                    u64 BR2, u64 BRN2, u64 BIP, int lane) {
    if constexpr (BIT >= 4) {
        constexpr int m = 1 << (BIT - 4);
        bool hi = (lane >> (BIT - 4)) & 1;
        u64 DIP = hi ? AIN : AIP;
        u64 OR2 = hi ? BRN2 : BR2;
#pragma unroll
        for (int j = 0; j < 16; j++) {
            u64 q, qsw;
            shfl_pk_both(v[j], m, q, qsw);
            u64 vsw = sw2(v[j]);
            v[j] = fma2(AR2, v[j], fma2(DIP, vsw, fma2(OR2, q, mul2(BIP, qsw))));
        }
    } else {
        constexpr int m = 1 << BIT;
#pragma unroll
        for (int j0 = 0; j0 < 16; j0++) {
            if ((j0 & m) == 0) {
                const int j1 = j0 | m;
                u64 v0 = v[j0], v1 = v[j1];
                u64 sw0 = sw2(v0), sw1 = sw2(v1);
                v[j0] = fma2(AR2, v0, fma2(AIP, sw0, fma2(BR2,  v1, mul2(BIP, sw1))));
                v[j1] = fma2(BRN2, v0, fma2(BIP, sw0, fma2(AR2, v1, mul2(AIN, sw1))));
            }
        }
    }
}

// CU = CNOT(ctl, tgt) o U(tgt)
template<int CB, int TB>
__device__ __forceinline__ void cu_g(u64 (&v)[16], const u64* __restrict__ g, int lane) {
    u64 AR2 = g[0], AIP = g[1], AIN = g[2], BR2 = g[3], BRN2 = g[4], BIP = g[5];
    if constexpr (TB >= 4) {
        constexpr int m = 1 << (TB - 4);
        bool hi = (lane >> (TB - 4)) & 1;
        if constexpr (CB >= 4) {
            bool ctl = (lane >> (CB - 4)) & 1;
            bool idx = ctl ? !hi : hi;
            u64 S1 = ctl ? (idx ? BRN2 : BR2) : AR2;
            u64 S2 = ctl ? BIP : (idx ? AIN : AIP);
            u64 T1 = ctl ? AR2 : (idx ? BRN2 : BR2);
            u64 T2 = ctl ? (idx ? AIN : AIP) : BIP;
#pragma unroll
            for (int j = 0; j < 16; j++) {
                u64 q, qsw;
                shfl_pk_both(v[j], m, q, qsw);
                u64 vsw = sw2(v[j]);
                v[j] = fma2(S1, v[j], fma2(S2, vsw, fma2(T1, q, mul2(T2, qsw))));
            }
        } else {
            constexpr int mc = 1 << CB;
            u64 S1a = AR2,               S2a = hi ? AIN : AIP;
            u64 T1a = hi ? BRN2 : BR2,   T2a = BIP;
            u64 S1b = (!hi) ? BRN2 : BR2, S2b = BIP;
            u64 T1b = AR2,                T2b = (!hi) ? AIN : AIP;
#pragma unroll
            for (int j = 0; j < 16; j++) {
                u64 q, qsw;
                shfl_pk_both(v[j], m, q, qsw);
                u64 vsw = sw2(v[j]);
                if (j & mc)
                    v[j] = fma2(S1b, v[j], fma2(S2b, vsw, fma2(T1b, q, mul2(T2b, qsw))));
                else
                    v[j] = fma2(S1a, v[j], fma2(S2a, vsw, fma2(T1a, q, mul2(T2a, qsw))));
            }
        }
    } else {
        constexpr int m = 1 << TB;
        if constexpr (CB >= 4) {
            bool ctl = (lane >> (CB - 4)) & 1;
#pragma unroll
            for (int j0 = 0; j0 < 16; j0++) {
                if ((j0 & m) == 0) {
                    const int j1 = j0 | m;
                    u64 v0 = v[j0], v1 = v[j1];
                    u64 sw0 = sw2(v0), sw1 = sw2(v1);
                    u64 n0 = fma2(AR2, v0, fma2(AIP, sw0, fma2(BR2,  v1, mul2(BIP, sw1))));
                    u64 n1 = fma2(BRN2, v0, fma2(BIP, sw0, fma2(AR2, v1, mul2(AIN, sw1))));
                    v[j0] = ctl ? n1 : n0;
                    v[j1] = ctl ? n0 : n1;
                }
            }
        } else {
            constexpr int mc = 1 << CB;
#pragma unroll
            for (int j0 = 0; j0 < 16; j0++) {
                if ((j0 & m) == 0) {
                    const int j1 = j0 | m;
                    u64 v0 = v[j0], v1 = v[j1];
                    u64 sw0 = sw2(v0), sw1 = sw2(v1);
                    u64 n0 = fma2(AR2, v0, fma2(AIP, sw0, fma2(BR2,  v1, mul2(BIP, sw1))));
                    u64 n1 = fma2(BRN2, v0, fma2(BIP, sw0, fma2(AR2, v1, mul2(AIN, sw1))));
                    if (j0 & mc) { v[j0] = n1; v[j1] = n0; }
                    else         { v[j0] = n0; v[j1] = n1; }
                }
            }
        }
    }
}

// ---- Plan-driven emission (bits via PERM, all as template args) ----
template<int E>
__device__ __forceinline__ void run_emit(u64 (&v)[16], const u64* __restrict__ s_rot,
                                         const u64* __restrict__ s_mats, int lane) {
    if constexpr (E < NEMIT) {
        constexpr int ty = PLAN.etype[E];
        if constexpr (ty == 0) {
            cnot_g<PERM.wbit[PLAN.ew[E]], PERM.wbit[PLAN.ew2[E]]>(v, lane);
        } else if constexpr (ty == 1) {
            constexpr int m = PLAN.ew2[E];
            const u64* g = s_mats + m * 6;
            u_g<PERM.wbit[PLAN.ew[E]]>(v, g[0], g[1], g[2], g[3], g[4], g[5], lane);
        } else if constexpr (ty == 2) {
            constexpr int k = PLAN.ew2[E];
            constexpr int kd = PLAN.ekind[E];
            const u64* g = s_rot + k * 5;
            constexpr int bit = PERM.wbit[PLAN.ew[E]];
            if constexpr (kd == 0)      rx_g<bit>(v, g[0], g[3], lane);
            else if constexpr (kd == 1) ry_g<bit>(v, g[0], g[1], g[2], lane);
            else                        rz_g<bit>(v, g[0], g[3], g[4], lane);
        } else {
            constexpr int m = PLAN.ekind[E];
            cu_g<PERM.wbit[PLAN.ew[E]], PERM.wbit[PLAN.ew2[E]]>(v, s_mats + m * 6, lane);
        }
        run_emit<E + 1>(v, s_rot, s_mats, lane);
    }
}

// ---- SU(2) composition (preamble): acc' = R * acc ----
__device__ void compose_su2(const int* ks, const int* kds, int len,
                            const float* __restrict__ rl, float tx, float ty,
                            float& ar, float& ai, float& br, float& bi) {
    ar = 1.f; ai = 0.f; br = 0.f; bi = 0.f;
    for (int i = 0; i < len; i++) {
        int k = ks[i], kd = kds[i];
        float ang = (k >= 0) ? rl[k] * 0.5f : ((k == -1) ? tx * 0.5f : ty * 0.5f);
        float c, s; sincosf(ang, &s, &c);
        float xr, xi, yr, yi;
        if (kd == 0)      { xr = c; xi = 0.f; yr = 0.f; yi = -s; }  // RX
        else if (kd == 1) { xr = c; xi = 0.f; yr = -s;  yi = 0.f; } // RY
        else              { xr = c; xi = -s;  yr = 0.f; yi = 0.f; } // RZ
        float na_r = xr * ar - xi * ai - (yr * br + yi * bi);
        float na_i = xr * ai + xi * ar - (yi * br - yr * bi);
        float nb_r = xr * br - xi * bi + (yr * ar + yi * ai);
        float nb_i = xr * bi + xi * br + (yi * ar - yr * ai);
        ar = na_r; ai = na_i; br = nb_r; bi = nb_i;
    }
}

// ---- Init product accumulation (wire->bit via PERM, compile-time only) ----
template<int W>
__device__ __forceinline__ void gammas(u64 (&g0)[8], u64 (&g1)[8],
                                       const float* cw, const float* sw,
                                       const u64* __restrict__ s_pre) {
    if constexpr (W < 8) {
        if constexpr (PLAN.pre_len[W] > 0) {
            const u64* pp = s_pre + W * 4;
            u64 C2 = pk2(cw[W], cw[W]), S2 = pk2(sw[W], sw[W]);
            g0[W] = fma2(S2, pp[2], mul2(C2, pp[0]));
            g1[W] = fma2(S2, pp[1], mul2(C2, pp[3]));
        }
        gammas<W + 1>(g0, g1, cw, sw, s_pre);
    }
}

template<int W>
__device__ __forceinline__ void t_accum(float& R, u64& C, int t,
                                        const float* cw, const float* sw,
                                        const u64 (&g0)[8], const u64 (&g1)[8]) {
    if constexpr (W < 8) {
        if constexpr (PERM.wbit[W] >= 4) {
            constexpr int tb = PERM.wbit[W] - 4;
            if constexpr (PLAN.pre_len[W] > 0) {
                u64 g = ((t >> tb) & 1) ? g1[W] : g0[W];
                if constexpr (W == FT) C = g; else C = cmul(C, g);
            } else {
                R *= ((t >> tb) & 1) ? sw[W] : cw[W];
            }
        }
        t_accum<W + 1>(R, C, t, cw, sw, g0, g1);
    }
}

template<int W>
__device__ __forceinline__ void j_accum(float& R, u64& C, int j,
                                        const float* cw, const float* sw,
                                        const u64 (&g0)[8], const u64 (&g1)[8]) {
    if constexpr (W < 8) {
        if constexpr (PERM.wbit[W] < 4) {
            constexpr int jb = PERM.wbit[W];
            if constexpr (PLAN.pre_len[W] > 0) {
                u64 g = ((j >> jb) & 1) ? g1[W] : g0[W];
                if constexpr (W == FJ) C = g; else C = cmul(C, g);
            } else {
                R *= ((j >> jb) & 1) ? sw[W] : cw[W];
            }
        }
        j_accum<W + 1>(R, C, j, cw, sw, g0, g1);
    }
}

// ===========================================================================
// Main kernel: one warp per TWO batch items, 16 packed amps per lane.
// __launch_bounds__(256, 5): cap regs at ~51 to lift occupancy 44.5% -> ~62%.
// ===========================================================================
__global__ __launch_bounds__(256, 5)
void qcnn_kernel(const float* __restrict__ x,
                 const float* __restrict__ rl,
                 const float* __restrict__ trx,
                 const float* __restrict__ tryy,
                 float* __restrict__ out, int bsz) {
    __shared__ u64 s_rot[N_OPS_C * 5];
    __shared__ u64 s_mats[NMAT * 6];
    __shared__ u64 s_pre[8 * 4];

    int tid = threadIdx.x;
    if (tid < N_OPS_C) {
        float c, s;
        sincosf(rl[tid] * 0.5f, &s, &c);
        u64* g = s_rot + tid * 5;
        g[0] = pk2(c, c);  g[1] = pk2(s, s);   g[2] = pk2(-s, -s);
        g[3] = pk2(s, -s); g[4] = pk2(-s, s);
    } else if (tid >= 32 && tid < 32 + NMAT) {
        int m = tid - 32;
        float ar, ai, br, bi;
        compose_su2(d_PLAN.mk[m], d_PLAN.mkind[m], d_PLAN.mlen[m],
                    rl, trx[0], tryy[0], ar, ai, br, bi);
        u64* g = s_mats + m * 6;
        g[0] = pk2(ar, ar);   g[1] = pk2(-ai, ai);  g[2] = pk2(ai, -ai);
        g[3] = pk2(br, br);   g[4] = pk2(-br, -br); g[5] = pk2(-bi, bi);
    } else if (tid >= 96 && tid < 104) {
        int w = tid - 96;
        if (d_PLAN.pre_len[w] > 0) {
            float ar, ai, br, bi;
            compose_su2(d_PLAN.pre_k[w], d_PLAN.pre_kind[w], d_PLAN.pre_len[w],
                        rl, trx[0], tryy[0], ar, ai, br, bi);
            u64* g = s_pre + w * 4;
            g[0] = pk2(ar, ai); g[1] = pk2(ar, -ai);
            g[2] = pk2(br, bi); g[3] = pk2(-br, bi);
        }
    }
    __syncthreads();

    int warp = blockIdx.x * (blockDim.x >> 5) + (tid >> 5);
    int lane = tid & 31;
    int t = lane & 15;
    long b = (long)warp * 2 + (lane >> 4);
    if (b >= bsz) return;

    // ---- Init: product state with pre-touch rotations absorbed per wire ----
    float myc, mys;
    float ang = (t < 8) ? __ldg(x + b * 8 + t) * 0.5f : 0.0f;
    sincosf(ang, &mys, &myc);
    float cw[8], sw[8];
#pragma unroll
    for (int w = 0; w < 8; w++) {
        int src = (lane & 16) | w;
        cw[w] = __shfl_sync(FULL, myc, src);
        sw[w] = __shfl_sync(FULL, mys, src);
    }
    u64 g0[8], g1[8];
    gammas<0>(g0, g1, cw, sw, s_pre);

    float Rt = 1.0f; u64 Ct = 0;
    t_accum<0>(Rt, Ct, t, cw, sw, g0, g1);

    u64 v[16];
#pragma unroll
    for (int j = 0; j < 16; j++) {
        float R = Rt; u64 Cj = 0;
        j_accum<0>(R, Cj, j, cw, sw, g0, g1);
        if constexpr (FT >= 0 && FJ >= 0) v[j] = mul2(pk2(R, R), cmul(Ct, Cj));
        else if constexpr (FT >= 0)       v[j] = mul2(pk2(R, R), Ct);
        else if constexpr (FJ >= 0)       v[j] = mul2(pk2(R, R), Cj);
        else                              v[j] = pk2(R, 0.0f);
    }

    // ---- Compiled circuit ----
    run_emit<0>(v, s_rot, s_mats, lane);

    // ---- Readout ----
    // A_b = Z-sum partials for LOCAL bit b; S feeds the FWHT for lane bits.
    float S = 0.f, A0 = 0.f, A1 = 0.f, A2 = 0.f, A3 = 0.f;
#pragma unroll
    for (int j = 0; j < 16; j++) {
        float r, i; upk2(v[j], r, i);
        float pj = fmaf(r, r, i * i);
        S  += pj;
        A0 += (j & 1)        ? -pj : pj;
        A1 += ((j >> 1) & 1) ? -pj : pj;
        A2 += ((j >> 2) & 1) ? -pj : pj;
        A3 += ((j >> 3) & 1) ? -pj : pj;
    }
#pragma unroll
    for (int off = 8; off; off >>= 1) {
        float pS = __shfl_xor_sync(FULL, S,  off);
        float p0 = __shfl_xor_sync(FULL, A0, off);
        float p1 = __shfl_xor_sync(FULL, A1, off);
        float p2 = __shfl_xor_sync(FULL, A2, off);
        float p3 = __shfl_xor_sync(FULL, A3, off);
        S  = (lane & off) ? (pS - S) : (S + pS);
        A0 += p0; A1 += p1; A2 += p2; A3 += p3;
    }
    // Lane t=2^k holds ZS for lane bit k (global bit 4+k) -> wire WOFB_HI byte k.
    float* o = out + (size_t)b * 8;
    if (t && !(t & (t - 1))) {
        int k = __ffs(t) - 1;
        o[(WOFB_HI >> (8 * k)) & 0xff] = S;
    }
    if (t == 0) {
        o[WOFB_LO0] = A0; o[WOFB_LO1] = A1;
        o[WOFB_LO2] = A2; o[WOFB_LO3] = A3;
    }
}

extern "C" void kernel_launch(void* const* d_in, const int* in_sizes, int n_in,
                              void* d_out, int out_size) {
    const float* x    = (const float*)d_in[0];
    const float* rl   = (const float*)d_in[1];
    const float* trx  = (const float*)d_in[2];
    const float* tryy = (const float*)d_in[3];
    float* out = (float*)d_out;

    int bsz = in_sizes[0] / N_QUBITS_C;

    int warps_per_block = 8;
    int items_per_block = warps_per_block * 2;
    dim3 block(warps_per_block * 32);
    dim3 grid((bsz + items_per_block - 1) / items_per_block);
    qcnn_kernel<<<grid, block>>>(x, rl, trx, tryy, out, bsz);
}

// round 13
// speedup vs baseline: 1.0036x; 1.0036x over previous
#include <cuda_runtime.h>
#include <cstdint>

#define FULL 0xffffffffu
#define N_OPS_C 20
#define N_QUBITS_C 8

using u64 = unsigned long long;

// ===========================================================================
// Compile-time reproduction of np.random.RandomState(0) draws for _RL_OPS
// (validated across R1/R3/R4/R5/R6/R7/R11: rel_err ~2e-7..3.5e-7).
// ===========================================================================
struct OpsArr { int op[N_OPS_C]; };  // kind | (w0<<2) | (w1<<5); 0=rx 1=ry 2=rz 3=cnot

struct CxRng {
    uint32_t mt[624]; int mti;
    constexpr CxRng() : mt{}, mti(624) {
        mt[0] = 0u;
        for (int i = 1; i < 624; i++)
            mt[i] = 1812433253u * (mt[i - 1] ^ (mt[i - 1] >> 30)) + (uint32_t)i;
    }
    constexpr uint32_t next() {
        if (mti >= 624) {
            for (int i = 0; i < 624; i++) {
                uint32_t y = (mt[i] & 0x80000000u) | (mt[(i + 1) % 624] & 0x7fffffffu);
                mt[i] = mt[(i + 397) % 624] ^ (y >> 1) ^ ((y & 1u) ? 0x9908b0dfu : 0u);
            }
            mti = 0;
        }
        uint32_t y = mt[mti++];
        y ^= y >> 11;
        y ^= (y << 7) & 0x9d2c5680u;
        y ^= (y << 15) & 0xefc60000u;
        y ^= y >> 18;
        return y;
    }
    constexpr uint32_t interval(uint32_t mx) {
        if (mx == 0u) return 0u;
        uint32_t mask = mx;
        mask |= mask >> 1; mask |= mask >> 2; mask |= mask >> 4;
        mask |= mask >> 8; mask |= mask >> 16;
        uint32_t v = next() & mask;
        while (v > mx) v = next() & mask;
        return v;
    }
};

constexpr OpsArr build_ops_cx() {
    CxRng rng{};
    OpsArr ol{};
    for (int k = 0; k < N_OPS_C; k++) {
        int kd = (int)(rng.next() & 3u);
        int w0 = 0, w1 = 0;
        if (kd == 3) {
            int perm[8] = {0, 1, 2, 3, 4, 5, 6, 7};
            for (int i = 7; i > 0; i--) {
                uint32_t j = rng.interval((uint32_t)i);
                int t = perm[i]; perm[i] = perm[(int)j]; perm[(int)j] = t;
            }
            w0 = perm[0]; w1 = perm[1];
        } else {
            w0 = (int)(rng.next() & 7u);
        }
        ol.op[k] = kd | (w0 << 2) | (w1 << 5);
    }
    return ol;
}

constexpr OpsArr OPS = build_ops_cx();

// ===========================================================================
// Compile-time circuit compiler v3 (CU fusion + commutation deferral
// + wire->bit permutation minimizing shuffle passes).
// ===========================================================================
struct Plan {
    int n_emit;
    int etype[48], ew[48], ew2[48], ekind[48];
    int n_mat;
    int mlen[32], mk[32][24], mkind[32][24];
    int pre_len[8], pre_k[8][20], pre_kind[8][20];
};

constexpr Plan build_plan() {
    Plan P{};
    int plen[8] = {}; int pk[8][20] = {}; int pkd[8][20] = {};
    bool seen[8] = {};
    for (int k = 0; k < N_OPS_C; k++) {
        int o = OPS.op[k]; int kd = o & 3;
        int w0 = (o >> 2) & 7, w1 = (o >> 5) & 7;
        if (kd != 3) {
            pk[w0][plen[w0]] = k; pkd[w0][plen[w0]] = kd; plen[w0]++;
            continue;
        }
        int c = w0, t = w1;
        if (!seen[c]) {
            P.pre_len[c] = plen[c];
            for (int i = 0; i < plen[c]; i++) {
                P.pre_k[c][i] = pk[c][i]; P.pre_kind[c][i] = pkd[c][i];
            }
            plen[c] = 0;
        } else {
            int split = plen[c];
            while (split > 0 && pkd[c][split - 1] == 2) split--;  // defer RZ suffix
            if (split == 1) {
                P.etype[P.n_emit] = 2; P.ew[P.n_emit] = c;
                P.ew2[P.n_emit] = pk[c][0]; P.ekind[P.n_emit] = pkd[c][0];
                P.n_emit++;
            } else if (split > 1) {
                int m = P.n_mat++;
                P.mlen[m] = split;
                for (int i = 0; i < split; i++) {
                    P.mk[m][i] = pk[c][i]; P.mkind[m][i] = pkd[c][i];
                }
                P.etype[P.n_emit] = 1; P.ew[P.n_emit] = c; P.ew2[P.n_emit] = m;
                P.n_emit++;
            }
            for (int i = split; i < plen[c]; i++) {
                pk[c][i - split] = pk[c][i]; pkd[c][i - split] = pkd[c][i];
            }
            plen[c] -= split;
        }
        seen[c] = true;
        bool cu = false;
        if (!seen[t]) {
            P.pre_len[t] = plen[t];
            for (int i = 0; i < plen[t]; i++) {
                P.pre_k[t][i] = pk[t][i]; P.pre_kind[t][i] = pkd[t][i];
            }
            plen[t] = 0;
        } else {
            int split = plen[t];
            while (split > 0 && pkd[t][split - 1] == 0) split--;  // defer RX suffix
            if (split > 0) {
                int m = P.n_mat++;
                P.mlen[m] = split;
                for (int i = 0; i < split; i++) {
                    P.mk[m][i] = pk[t][i]; P.mkind[m][i] = pkd[t][i];
                }
                P.etype[P.n_emit] = 3; P.ew[P.n_emit] = c; P.ew2[P.n_emit] = t;
                P.ekind[P.n_emit] = m; P.n_emit++;
                cu = true;
            }
            for (int i = split; i < plen[t]; i++) {
                pk[t][i - split] = pk[t][i]; pkd[t][i - split] = pkd[t][i];
            }
            plen[t] -= split;
        }
        seen[t] = true;
        if (!cu) {
            P.etype[P.n_emit] = 0; P.ew[P.n_emit] = c; P.ew2[P.n_emit] = t;
            P.n_emit++;
        }
    }
    for (int w = 0; w < 8; w++) {
        int m = P.n_mat++;
        int L = 0;
        for (int i = 0; i < plen[w]; i++) {
            P.mk[m][L] = pk[w][i]; P.mkind[m][L] = pkd[w][i]; L++;
        }
        P.mk[m][L] = -1; P.mkind[m][L] = 0; L++;
        P.mk[m][L] = -2; P.mkind[m][L] = 1; L++;
        P.mlen[m] = L;
        P.etype[P.n_emit] = 1; P.ew[P.n_emit] = w; P.ew2[P.n_emit] = m;
        P.n_emit++;
    }
    return P;
}

constexpr Plan PLAN = build_plan();
__constant__ Plan d_PLAN = build_plan();
constexpr int NMAT  = PLAN.n_mat;
constexpr int NEMIT = PLAN.n_emit;

struct Perm { int wbit[8]; int wofb[8]; };

constexpr Perm build_perm() {
    int wgt[8] = {};
    for (int e = 0; e < PLAN.n_emit; e++) {
        int ty = PLAN.etype[e];
        if (ty == 0)      wgt[PLAN.ew2[e]]++;
        else if (ty == 1) wgt[PLAN.ew[e]]++;
        else if (ty == 2) { if (PLAN.ekind[e] != 2) wgt[PLAN.ew[e]]++; }
        else              wgt[PLAN.ew2[e]]++;
    }
    Perm P{};
    int order[8] = {0, 1, 2, 3, 4, 5, 6, 7};
    for (int i = 0; i < 8; i++) {
        int best = i;
        for (int k = i + 1; k < 8; k++)
            if (wgt[order[k]] > wgt[order[best]]) best = k;
        int t = order[i]; order[i] = order[best]; order[best] = t;
    }
    for (int i = 0; i < 8; i++) { P.wbit[order[i]] = i; P.wofb[i] = order[i]; }
    return P;
}

constexpr Perm PERM = build_perm();
constexpr int WOFB_HI = PERM.wofb[4] | (PERM.wofb[5] << 8)
                      | (PERM.wofb[6] << 16) | (PERM.wofb[7] << 24);
constexpr int WOFB_LO0 = PERM.wofb[0];
constexpr int WOFB_LO1 = PERM.wofb[1];
constexpr int WOFB_LO2 = PERM.wofb[2];
constexpr int WOFB_LO3 = PERM.wofb[3];

constexpr int first_lane_cplx() {
    for (int w = 0; w < 8; w++)
        if (PLAN.pre_len[w] > 0 && PERM.wbit[w] >= 4) return w;
    return -1;
}
constexpr int first_local_cplx() {
    for (int w = 0; w < 8; w++)
        if (PLAN.pre_len[w] > 0 && PERM.wbit[w] < 4) return w;
    return -1;
}
constexpr int FT = first_lane_cplx();
constexpr int FJ = first_local_cplx();

// ===========================================================================
// Packed f32x2 primitives. Amplitude = u64 packed (re = lo, im = hi).
// ===========================================================================
__device__ __forceinline__ u64 pk2(float lo, float hi) {
    u64 r; asm("mov.b64 %0, {%1, %2};" : "=l"(r) : "f"(lo), "f"(hi)); return r;
}
__device__ __forceinline__ void upk2(u64 v, float& lo, float& hi) {
    asm("mov.b64 {%0, %1}, %2;" : "=f"(lo), "=f"(hi) : "l"(v));
}
__device__ __forceinline__ u64 sw2(u64 v) {
    u64 r;
    asm("{\n\t.reg .b32 a, b;\n\tmov.b64 {a, b}, %1;\n\tmov.b64 %0, {b, a};\n\t}"
        : "=l"(r) : "l"(v));
    return r;
}
__device__ __forceinline__ u64 fma2(u64 a, u64 b, u64 c) {
    u64 d; asm("fma.rn.f32x2 %0, %1, %2, %3;" : "=l"(d) : "l"(a), "l"(b), "l"(c)); return d;
}
__device__ __forceinline__ u64 mul2(u64 a, u64 b) {
    u64 d; asm("mul.rn.f32x2 %0, %1, %2;" : "=l"(d) : "l"(a), "l"(b)); return d;
}
__device__ __forceinline__ u64 cmul(u64 p, u64 q) {
    float pr, pi_; upk2(p, pr, pi_);
    return fma2(pk2(-pi_, pi_), sw2(q), mul2(pk2(pr, pr), q));
}
__device__ __forceinline__ u64 shfl_pk(u64 v, int m) {
    float lo, hi; upk2(v, lo, hi);
    float plo = __shfl_xor_sync(FULL, lo, m);
    float phi = __shfl_xor_sync(FULL, hi, m);
    return pk2(plo, phi);
}
__device__ __forceinline__ u64 shfl_pk_sw(u64 v, int m) {
    float lo, hi; upk2(v, lo, hi);
    float plo = __shfl_xor_sync(FULL, lo, m);
    float phi = __shfl_xor_sync(FULL, hi, m);
    return pk2(phi, plo);
}
__device__ __forceinline__ void shfl_pk_both(u64 v, int m, u64& q, u64& qsw) {
    float lo, hi; upk2(v, lo, hi);
    float plo = __shfl_xor_sync(FULL, lo, m);
    float phi = __shfl_xor_sync(FULL, hi, m);
    q = pk2(plo, phi); qsw = pk2(phi, plo);
}

// ===========================================================================
// Layout: 2 items per warp, 16 lanes per item (group bit = lane bit 4).
// Amplitude index bits: [7:4] = sublane t (lane bits 3..0), [3:0] = local j.
// Wire w <-> bit PERM.wbit[w]. BIT>=4: lane gate; BIT<4: register-local.
// ===========================================================================

template<int BIT>
__device__ __forceinline__ void rx_g(u64 (&v)[16], u64 CC, u64 SPN, int lane) {
    if constexpr (BIT >= 4) {
        constexpr int m = 1 << (BIT - 4);
#pragma unroll
        for (int j = 0; j < 16; j++) {
            u64 psw = shfl_pk_sw(v[j], m);
            v[j] = fma2(SPN, psw, mul2(CC, v[j]));
        }
    } else {
        constexpr int m = 1 << BIT;
#pragma unroll
        for (int j0 = 0; j0 < 16; j0++) {
            if ((j0 & m) == 0) {
                const int j1 = j0 | m;
                u64 sw0 = sw2(v[j0]), sw1 = sw2(v[j1]);
                v[j0] = fma2(SPN, sw1, mul2(CC, v[j0]));
                v[j1] = fma2(SPN, sw0, mul2(CC, v[j1]));
            }
        }
    }
}

template<int BIT>
__device__ __forceinline__ void ry_g(u64 (&v)[16], u64 CC, u64 SS, u64 SN, int lane) {
    if constexpr (BIT >= 4) {
        constexpr int m = 1 << (BIT - 4);
        u64 ssP = ((lane >> (BIT - 4)) & 1) ? SS : SN;
#pragma unroll
        for (int j = 0; j < 16; j++) {
            u64 p = shfl_pk(v[j], m);
            v[j] = fma2(ssP, p, mul2(CC, v[j]));
        }
    } else {
        constexpr int m = 1 << BIT;
#pragma unroll
        for (int j0 = 0; j0 < 16; j0++) {
            if ((j0 & m) == 0) {
                const int j1 = j0 | m;
                u64 v0 = v[j0], v1 = v[j1];
                v[j0] = fma2(SN, v1, mul2(CC, v0));
                v[j1] = fma2(SS, v0, mul2(CC, v1));
            }
        }
    }
}

template<int BIT>
__device__ __forceinline__ void rz_g(u64 (&v)[16], u64 CC, u64 SPN, u64 NSP, int lane) {
    if constexpr (BIT >= 4) {
        u64 zc = ((lane >> (BIT - 4)) & 1) ? NSP : SPN;
#pragma unroll
        for (int j = 0; j < 16; j++)
            v[j] = fma2(zc, sw2(v[j]), mul2(CC, v[j]));
    } else {
        constexpr int m = 1 << BIT;
#pragma unroll
        for (int j = 0; j < 16; j++) {
            u64 zc = (j & m) ? NSP : SPN;
            v[j] = fma2(zc, sw2(v[j]), mul2(CC, v[j]));
        }
    }
}

template<int CB, int TB>
__device__ __forceinline__ void cnot_g(u64 (&v)[16], int lane) {
    if constexpr (CB >= 4 && TB >= 4) {
        constexpr int mt = 1 << (TB - 4);
        bool ctl = (lane >> (CB - 4)) & 1;
#pragma unroll
        for (int j = 0; j < 16; j++) {
            u64 q = shfl_pk(v[j], mt);
            if (ctl) v[j] = q;
        }
    } else if constexpr (CB >= 4 && TB < 4) {
        constexpr int mt = 1 << TB;
        bool ctl = (lane >> (CB - 4)) & 1;
#pragma unroll
        for (int j0 = 0; j0 < 16; j0++) {
            if ((j0 & mt) == 0) {
                const int j1 = j0 | mt;
                u64 a = v[j0], b = v[j1];
                v[j0] = ctl ? b : a;
                v[j1] = ctl ? a : b;
            }
        }
    } else if constexpr (CB < 4 && TB >= 4) {
        constexpr int mc = 1 << CB;
        constexpr int mt = 1 << (TB - 4);
#pragma unroll
        for (int j = 0; j < 16; j++) {
            if (j & mc)
                v[j] = shfl_pk(v[j], mt);
        }
    } else {
        constexpr int mc = 1 << CB;
        constexpr int mt = 1 << TB;
#pragma unroll
        for (int j0 = 0; j0 < 16; j0++) {
            if ((j0 & mc) && !(j0 & mt)) {
                const int j1 = j0 | mt;
                u64 t = v[j0]; v[j0] = v[j1]; v[j1] = t;
            }
        }
    }
}

// General SU(2) gate U = [[ar+i*ai, br+i*bi], [-br+i*bi, ar-i*ai]]
template<int BIT>
__device__ __forceinline__ void u_g(u64 (&v)[16],
                                    u64 AR2, u64 AIP, u64 AIN,
                                    u64 BR2, u64 BRN2, u64 BIP, int lane) {
    if constexpr (BIT >= 4) {
        constexpr int m = 1 << (BIT - 4);
        bool hi = (lane >> (BIT - 4)) & 1;
        u64 DIP = hi ? AIN : AIP;
        u64 OR2 = hi ? BRN2 : BR2;
#pragma unroll
        for (int j = 0; j < 16; j++) {
            u64 q, qsw;
            shfl_pk_both(v[j], m, q, qsw);
            u64 vsw = sw2(v[j]);
            v[j] = fma2(AR2, v[j], fma2(DIP, vsw, fma2(OR2, q, mul2(BIP, qsw))));
        }
    } else {
        constexpr int m = 1 << BIT;
#pragma unroll
        for (int j0 = 0; j0 < 16; j0++) {
            if ((j0 & m) == 0) {
                const int j1 = j0 | m;
                u64 v0 = v[j0], v1 = v[j1];
                u64 sw0 = sw2(v0), sw1 = sw2(v1);
                v[j0] = fma2(AR2, v0, fma2(AIP, sw0, fma2(BR2,  v1, mul2(BIP, sw1))));
                v[j1] = fma2(BRN2, v0, fma2(BIP, sw0, fma2(AR2, v1, mul2(AIN, sw1))));
            }
        }
    }
}

// CU = CNOT(ctl, tgt) o U(tgt)
template<int CB, int TB>
__device__ __forceinline__ void cu_g(u64 (&v)[16], const u64* __restrict__ g, int lane) {
    u64 AR2 = g[0], AIP = g[1], AIN = g[2], BR2 = g[3], BRN2 = g[4], BIP = g[5];
    if constexpr (TB >= 4) {
        constexpr int m = 1 << (TB - 4);
        bool hi = (lane >> (TB - 4)) & 1;
        if constexpr (CB >= 4) {
            bool ctl = (lane >> (CB - 4)) & 1;
            bool idx = ctl ? !hi : hi;
            u64 S1 = ctl ? (idx ? BRN2 : BR2) : AR2;
            u64 S2 = ctl ? BIP : (idx ? AIN : AIP);
            u64 T1 = ctl ? AR2 : (idx ? BRN2 : BR2);
            u64 T2 = ctl ? (idx ? AIN : AIP) : BIP;
#pragma unroll
            for (int j = 0; j < 16; j++) {
                u64 q, qsw;
                shfl_pk_both(v[j], m, q, qsw);
                u64 vsw = sw2(v[j]);
                v[j] = fma2(S1, v[j], fma2(S2, vsw, fma2(T1, q, mul2(T2, qsw))));
            }
        } else {
            constexpr int mc = 1 << CB;
            u64 S1a = AR2,               S2a = hi ? AIN : AIP;
            u64 T1a = hi ? BRN2 : BR2,   T2a = BIP;
            u64 S1b = (!hi) ? BRN2 : BR2, S2b = BIP;
            u64 T1b = AR2,                T2b = (!hi) ? AIN : AIP;
#pragma unroll
            for (int j = 0; j < 16; j++) {
                u64 q, qsw;
                shfl_pk_both(v[j], m, q, qsw);
                u64 vsw = sw2(v[j]);
                if (j & mc)
                    v[j] = fma2(S1b, v[j], fma2(S2b, vsw, fma2(T1b, q, mul2(T2b, qsw))));
                else
                    v[j] = fma2(S1a, v[j], fma2(S2a, vsw, fma2(T1a, q, mul2(T2a, qsw))));
            }
        }
    } else {
        constexpr int m = 1 << TB;
        if constexpr (CB >= 4) {
            bool ctl = (lane >> (CB - 4)) & 1;
#pragma unroll
            for (int j0 = 0; j0 < 16; j0++) {
                if ((j0 & m) == 0) {
                    const int j1 = j0 | m;
                    u64 v0 = v[j0], v1 = v[j1];
                    u64 sw0 = sw2(v0), sw1 = sw2(v1);
                    u64 n0 = fma2(AR2, v0, fma2(AIP, sw0, fma2(BR2,  v1, mul2(BIP, sw1))));
                    u64 n1 = fma2(BRN2, v0, fma2(BIP, sw0, fma2(AR2, v1, mul2(AIN, sw1))));
                    v[j0] = ctl ? n1 : n0;
                    v[j1] = ctl ? n0 : n1;
                }
            }
        } else {
            constexpr int mc = 1 << CB;
#pragma unroll
            for (int j0 = 0; j0 < 16; j0++) {
                if ((j0 & m) == 0) {
                    const int j1 = j0 | m;
                    u64 v0 = v[j0], v1 = v[j1];
                    u64 sw0 = sw2(v0), sw1 = sw2(v1);
                    u64 n0 = fma2(AR2, v0, fma2(AIP, sw0, fma2(BR2,  v1, mul2(BIP, sw1))));
                    u64 n1 = fma2(BRN2, v0, fma2(BIP, sw0, fma2(AR2, v1, mul2(AIN, sw1))));
                    if (j0 & mc) { v[j0] = n1; v[j1] = n0; }
                    else         { v[j0] = n0; v[j1] = n1; }
                }
            }
        }
    }
}

// ---- Plan-driven emission (bits via PERM, all as template args) ----
template<int E>
__device__ __forceinline__ void run_emit(u64 (&v)[16], const u64* __restrict__ s_rot,
                                         const u64* __restrict__ s_mats, int lane) {
    if constexpr (E < NEMIT) {
        constexpr int ty = PLAN.etype[E];
        if constexpr (ty == 0) {
            cnot_g<PERM.wbit[PLAN.ew[E]], PERM.wbit[PLAN.ew2[E]]>(v, lane);
        } else if constexpr (ty == 1) {
            constexpr int m = PLAN.ew2[E];
            const u64* g = s_mats + m * 6;
            u_g<PERM.wbit[PLAN.ew[E]]>(v, g[0], g[1], g[2], g[3], g[4], g[5], lane);
        } else if constexpr (ty == 2) {
            constexpr int k = PLAN.ew2[E];
            constexpr int kd = PLAN.ekind[E];
            const u64* g = s_rot + k * 5;
            constexpr int bit = PERM.wbit[PLAN.ew[E]];
            if constexpr (kd == 0)      rx_g<bit>(v, g[0], g[3], lane);
            else if constexpr (kd == 1) ry_g<bit>(v, g[0], g[1], g[2], lane);
            else                        rz_g<bit>(v, g[0], g[3], g[4], lane);
        } else {
            constexpr int m = PLAN.ekind[E];
            cu_g<PERM.wbit[PLAN.ew[E]], PERM.wbit[PLAN.ew2[E]]>(v, s_mats + m * 6, lane);
        }
        run_emit<E + 1>(v, s_rot, s_mats, lane);
    }
}

// ---- SU(2) composition (preamble): acc' = R * acc ----
__device__ void compose_su2(const int* ks, const int* kds, int len,
                            const float* __restrict__ rl, float tx, float ty,
                            float& ar, float& ai, float& br, float& bi) {
    ar = 1.f; ai = 0.f; br = 0.f; bi = 0.f;
    for (int i = 0; i < len; i++) {
        int k = ks[i], kd = kds[i];
        float ang = (k >= 0) ? rl[k] * 0.5f : ((k == -1) ? tx * 0.5f : ty * 0.5f);
        float c, s; sincosf(ang, &s, &c);
        float xr, xi, yr, yi;
        if (kd == 0)      { xr = c; xi = 0.f; yr = 0.f; yi = -s; }  // RX
        else if (kd == 1) { xr = c; xi = 0.f; yr = -s;  yi = 0.f; } // RY
        else              { xr = c; xi = -s;  yr = 0.f; yi = 0.f; } // RZ
        float na_r = xr * ar - xi * ai - (yr * br + yi * bi);
        float na_i = xr * ai + xi * ar - (yi * br - yr * bi);
        float nb_r = xr * br - xi * bi + (yr * ar + yi * ai);
        float nb_i = xr * bi + xi * br + (yi * ar - yr * ai);
        ar = na_r; ai = na_i; br = nb_r; bi = nb_i;
    }
}

// ---- Init product accumulation (wire->bit via PERM, compile-time only) ----
template<int W>
__device__ __forceinline__ void gammas(u64 (&g0)[8], u64 (&g1)[8],
                                       const float* cw, const float* sw,
                                       const u64* __restrict__ s_pre) {
    if constexpr (W < 8) {
        if constexpr (PLAN.pre_len[W] > 0) {
            const u64* pp = s_pre + W * 4;
            u64 C2 = pk2(cw[W], cw[W]), S2 = pk2(sw[W], sw[W]);
            g0[W] = fma2(S2, pp[2], mul2(C2, pp[0]));
            g1[W] = fma2(S2, pp[1], mul2(C2, pp[3]));
        }
        gammas<W + 1>(g0, g1, cw, sw, s_pre);
    }
}

template<int W>
__device__ __forceinline__ void t_accum(float& R, u64& C, int t,
                                        const float* cw, const float* sw,
                                        const u64 (&g0)[8], const u64 (&g1)[8]) {
    if constexpr (W < 8) {
        if constexpr (PERM.wbit[W] >= 4) {
            constexpr int tb = PERM.wbit[W] - 4;
            if constexpr (PLAN.pre_len[W] > 0) {
                u64 g = ((t >> tb) & 1) ? g1[W] : g0[W];
                if constexpr (W == FT) C = g; else C = cmul(C, g);
            } else {
                R *= ((t >> tb) & 1) ? sw[W] : cw[W];
            }
        }
        t_accum<W + 1>(R, C, t, cw, sw, g0, g1);
    }
}

template<int W>
__device__ __forceinline__ void j_accum(float& R, u64& C, int j,
                                        const float* cw, const float* sw,
                                        const u64 (&g0)[8], const u64 (&g1)[8]) {
    if constexpr (W < 8) {
        if constexpr (PERM.wbit[W] < 4) {
            constexpr int jb = PERM.wbit[W];
            if constexpr (PLAN.pre_len[W] > 0) {
                u64 g = ((j >> jb) & 1) ? g1[W] : g0[W];
                if constexpr (W == FJ) C = g; else C = cmul(C, g);
            } else {
                R *= ((j >> jb) & 1) ? sw[W] : cw[W];
            }
        }
        j_accum<W + 1>(R, C, j, cw, sw, g0, g1);
    }
}

// ===========================================================================
// Main kernel: PERSISTENT. One warp handles TWO items per iteration and
// grid-strides over item-pairs. Grid sized to exactly fill the chip (4
// blocks/SM at ~60 regs), eliminating block-wave quantization (~13% idle).
// ===========================================================================
__global__ __launch_bounds__(256)
void qcnn_kernel(const float* __restrict__ x,
                 const float* __restrict__ rl,
                 const float* __restrict__ trx,
                 const float* __restrict__ tryy,
                 float* __restrict__ out, int bsz) {
    __shared__ u64 s_rot[N_OPS_C * 5];
    __shared__ u64 s_mats[NMAT * 6];
    __shared__ u64 s_pre[8 * 4];

    int tid = threadIdx.x;
    if (tid < N_OPS_C) {
        float c, s;
        sincosf(rl[tid] * 0.5f, &s, &c);
        u64* g = s_rot + tid * 5;
        g[0] = pk2(c, c);  g[1] = pk2(s, s);   g[2] = pk2(-s, -s);
        g[3] = pk2(s, -s); g[4] = pk2(-s, s);
    } else if (tid >= 32 && tid < 32 + NMAT) {
        int m = tid - 32;
        float ar, ai, br, bi;
        compose_su2(d_PLAN.mk[m], d_PLAN.mkind[m], d_PLAN.mlen[m],
                    rl, trx[0], tryy[0], ar, ai, br, bi);
        u64* g = s_mats + m * 6;
        g[0] = pk2(ar, ar);   g[1] = pk2(-ai, ai);  g[2] = pk2(ai, -ai);
        g[3] = pk2(br, br);   g[4] = pk2(-br, -br); g[5] = pk2(-bi, bi);
    } else if (tid >= 96 && tid < 104) {
        int w = tid - 96;
        if (d_PLAN.pre_len[w] > 0) {
            float ar, ai, br, bi;
            compose_su2(d_PLAN.pre_k[w], d_PLAN.pre_kind[w], d_PLAN.pre_len[w],
                        rl, trx[0], tryy[0], ar, ai, br, bi);
            u64* g = s_pre + w * 4;
            g[0] = pk2(ar, ai); g[1] = pk2(ar, -ai);
            g[2] = pk2(br, bi); g[3] = pk2(-br, bi);
        }
    }
    __syncthreads();

    int lane = tid & 31;
    int t = lane & 15;
    long nPairs = ((long)bsz + 1) / 2;
    long gw0 = (long)blockIdx.x * (blockDim.x >> 5) + (tid >> 5);
    long stride = (long)gridDim.x * (blockDim.x >> 5);

    for (long pair = gw0; pair < nPairs; pair += stride) {
        long b = pair * 2 + (lane >> 4);
        bool valid = b < bsz;

        // ---- Init: product state with pre-touch rotations absorbed ----
        float myc, mys;
        float ang = (valid && t < 8) ? __ldg(x + b * 8 + t) * 0.5f : 0.0f;
        sincosf(ang, &mys, &myc);
        float cw[8], sw[8];
#pragma unroll
        for (int w = 0; w < 8; w++) {
            int src = (lane & 16) | w;
            cw[w] = __shfl_sync(FULL, myc, src);
            sw[w] = __shfl_sync(FULL, mys, src);
        }
        u64 g0[8], g1[8];
        gammas<0>(g0, g1, cw, sw, s_pre);

        float Rt = 1.0f; u64 Ct = 0;
        t_accum<0>(Rt, Ct, t, cw, sw, g0, g1);

        u64 v[16];
#pragma unroll
        for (int j = 0; j < 16; j++) {
            float R = Rt; u64 Cj = 0;
            j_accum<0>(R, Cj, j, cw, sw, g0, g1);
            if constexpr (FT >= 0 && FJ >= 0) v[j] = mul2(pk2(R, R), cmul(Ct, Cj));
            else if constexpr (FT >= 0)       v[j] = mul2(pk2(R, R), Ct);
            else if constexpr (FJ >= 0)       v[j] = mul2(pk2(R, R), Cj);
            else                              v[j] = pk2(R, 0.0f);
        }

        // ---- Compiled circuit ----
        run_emit<0>(v, s_rot, s_mats, lane);

        // ---- Readout ----
        float S = 0.f, A0 = 0.f, A1 = 0.f, A2 = 0.f, A3 = 0.f;
#pragma unroll
        for (int j = 0; j < 16; j++) {
            float r, i; upk2(v[j], r, i);
            float pj = fmaf(r, r, i * i);
            S  += pj;
            A0 += (j & 1)        ? -pj : pj;
            A1 += ((j >> 1) & 1) ? -pj : pj;
            A2 += ((j >> 2) & 1) ? -pj : pj;
            A3 += ((j >> 3) & 1) ? -pj : pj;
        }
#pragma unroll
        for (int off = 8; off; off >>= 1) {
            float pS = __shfl_xor_sync(FULL, S,  off);
            float p0 = __shfl_xor_sync(FULL, A0, off);
            float p1 = __shfl_xor_sync(FULL, A1, off);
            float p2 = __shfl_xor_sync(FULL, A2, off);
            float p3 = __shfl_xor_sync(FULL, A3, off);
            S  = (lane & off) ? (pS - S) : (S + pS);
            A0 += p0; A1 += p1; A2 += p2; A3 += p3;
        }
        if (valid) {
            float* o = out + (size_t)b * 8;
            if (t && !(t & (t - 1))) {
                int k = __ffs(t) - 1;
                o[(WOFB_HI >> (8 * k)) & 0xff] = S;
            }
            if (t == 0) {
                o[WOFB_LO0] = A0; o[WOFB_LO1] = A1;
                o[WOFB_LO2] = A2; o[WOFB_LO3] = A3;
            }
        }
    }
}

extern "C" void kernel_launch(void* const* d_in, const int* in_sizes, int n_in,
                              void* d_out, int out_size) {
    const float* x    = (const float*)d_in[0];
    const float* rl   = (const float*)d_in[1];
    const float* trx  = (const float*)d_in[2];
    const float* tryy = (const float*)d_in[3];
    float* out = (float*)d_out;

    int bsz = in_sizes[0] / N_QUBITS_C;
    long nPairs = ((long)bsz + 1) / 2;

    int warps_per_block = 8;
    dim3 block(warps_per_block * 32);
    // Persistent: exactly fill the chip (148 SMs x 4 resident blocks @ ~60 regs).
    long maxBlocks = 148L * 4;
    long needBlocks = (nPairs + warps_per_block - 1) / warps_per_block;
    dim3 grid((unsigned)(needBlocks < maxBlocks ? needBlocks : maxBlocks));
    qcnn_kernel<<<grid, block>>>(x, rl, trx, tryy, out, bsz);
}